// round 3
// baseline (speedup 1.0000x reference)
#include <cuda_runtime.h>
#include <math.h>

// ---------------- problem constants ----------------
#define DIMC      64
#define HW        256          // 16x16
#define BATCH     256
#define EMB_DIM   45184
#define OFF_CNNW  0
#define OFF_CNNB  36864
#define OFF_PROJW 36928
#define OFF_PROJB 45120
#define BHW       (BATCH*DIMC*HW)   // 4194304 floats = 16 MB

typedef unsigned long long ull_t;

// packed f32x2 helpers (sm_103a FFMA2 path — only reachable via PTX)
#define PACKF2(out, lo, hi) \
    asm("mov.b64 %0, {%1, %2};" : "=l"(out) : "f"(lo), "f"(hi))
#define UNPACKF2(lo, hi, in) \
    asm("mov.b64 {%0, %1}, %2;" : "=f"(lo), "=f"(hi) : "l"(in))
#define FMAF2(d, a, b, c) \
    asm("fma.rn.f32x2 %0, %1, %2, %3;" : "=l"(d) : "l"(a), "l"(b), "l"(c))

// scratch: module outputs h1,h2 and projected conv-input
__device__ float g_h1[BHW];
__device__ float g_h2[BHW];
__device__ float g_ci[BHW];

__device__ __forceinline__ void softmax_n(const float* x, float* y, int n) {
    float m = x[0];
    for (int i = 1; i < n; i++) m = fmaxf(m, x[i]);
    float s = 0.f;
    for (int i = 0; i < n; i++) { y[i] = expf(x[i] - m); s += y[i]; }
    float inv = 1.f / s;
    for (int i = 0; i < n; i++) y[i] *= inv;
}

// =====================================================================
// Kernel P: per-batch projection (f32x2 packed).
//   ci[b, c, p] = sum_j proj_w[b,c,j] * inp[b,j,p] + proj_b[b,c]
// grid 256 (1 CTA/batch), 256 threads, 2 CTAs/SM.
// Positions packed in x-pairs (2*px, 2*px+1): bv2 = direct LDS.64.
// Weights duplicated (w,w) in smem (stride 140 words): av2 via LDS.128.
// =====================================================================
#define P_WSTRIDE 140
#define P_SMEM_FLOATS (16384 + 64*P_WSTRIDE + 64 + 16)

__global__ void __launch_bounds__(256, 2)
proj_kernel(const int* __restrict__ question,
            const float* __restrict__ img,
            const float* __restrict__ emb,
            const float* __restrict__ alpha,
            const float* __restrict__ tau0,
            const float* __restrict__ tau1,
            int mod)
{
    extern __shared__ float sm[];
    float* s_stage = sm;                        // 64*256 = 16384
    float* s_wTd   = sm + 16384;                // 64 * 140 (k-major, dup pairs)
    float* s_pb    = sm + 16384 + 64*P_WSTRIDE; // 64
    float* s_scal  = s_pb + 64;                 // 9 scalars

    const int b   = blockIdx.x;
    const int tid = threadIdx.x;

    if (tid == 0) {
        float tmp[4], sf[4];
        for (int t = 0; t < 3; t++) tmp[t] = alpha[mod*3 + t];
        softmax_n(tmp, sf, 3);
        s_scal[0] = sf[0]; s_scal[1] = sf[1]; s_scal[2] = sf[2];
        const int n = mod + 2;
        for (int m = 0; m < n; m++) tmp[m] = tau0[mod*4 + m];
        softmax_n(tmp, sf, n);
        s_scal[3] = sf[1];
        s_scal[4] = (n > 2) ? sf[2] : 0.f;
        s_scal[5] = (n > 3) ? sf[3] : 0.f;
        for (int m = 0; m < n; m++) tmp[m] = tau1[mod*4 + m];
        softmax_n(tmp, sf, n);
        s_scal[6] = sf[1];
        s_scal[7] = (n > 2) ? sf[2] : 0.f;
        s_scal[8] = (n > 3) ? sf[3] : 0.f;
    }
    __syncthreads();

    const float a0 = s_scal[0], a1 = s_scal[1], a2 = s_scal[2];
    const float* r0 = emb + (size_t)question[b*3 + 0] * EMB_DIM;
    const float* r1 = emb + (size_t)question[b*3 + 1] * EMB_DIM;
    const float* r2 = emb + (size_t)question[b*3 + 2] * EMB_DIM;

    if (tid < 64)
        s_pb[tid] = a0*r0[OFF_PROJB + tid] + a1*r1[OFF_PROJB + tid] + a2*r2[OFF_PROJB + tid];

    const int px = tid & 31;
    const int c0 = (tid >> 5) * 8;
    ull_t acc2[8][4];

    const float4* img4 = (const float4*)(img  + (size_t)b * DIMC * HW);
    const float4* h14  = (const float4*)(g_h1 + (size_t)b * DIMC * HW);
    const float4* h24  = (const float4*)(g_h2 + (size_t)b * DIMC * HW);
    float4* stage4 = (float4*)s_stage;

    for (int half = 0; half < 2; ++half) {
        const float w1 = s_scal[3 + 3*half + 0];
        const float w2 = s_scal[3 + 3*half + 1];
        const float w3 = s_scal[3 + 3*half + 2];

        // stage = w1*img + w2*h1 + w3*h2   (64 ch x 256 pos)
        for (int e4 = tid; e4 < 4096; e4 += 256) {
            float4 v = img4[e4];
            float4 o;
            o.x = w1*v.x; o.y = w1*v.y; o.z = w1*v.z; o.w = w1*v.w;
            if (mod >= 1) { float4 u = h14[e4]; o.x += w2*u.x; o.y += w2*u.y; o.z += w2*u.z; o.w += w2*u.w; }
            if (mod >= 2) { float4 u = h24[e4]; o.x += w3*u.x; o.y += w3*u.y; o.z += w3*u.z; o.w += w3*u.w; }
            stage4[e4] = o;
        }
        // proj weight (this K-half), k-major, DUPLICATED pairs: [kk*140 + 2c {+0,+1}]
        for (int e = tid; e < 4096; e += 256) {
            const int c  = e >> 6;
            const int kk = e & 63;
            const int off = OFF_PROJW + c*128 + half*64 + kk;
            const float v = a0*r0[off] + a1*r1[off] + a2*r2[off];
            const int w = kk*P_WSTRIDE + 2*c;
            s_wTd[w]     = v;
            s_wTd[w + 1] = v;
        }
        __syncthreads();

        if (half == 0) {
            #pragma unroll
            for (int ii = 0; ii < 8; ii++) {
                ull_t pbp;
                PACKF2(pbp, s_pb[c0 + ii], s_pb[c0 + ii]);
                #pragma unroll
                for (int j2 = 0; j2 < 4; j2++) acc2[ii][j2] = pbp;
            }
        }

        #pragma unroll 2
        for (int k = 0; k < 64; k++) {
            const ulonglong2* wq = (const ulonglong2*)(s_wTd + k*P_WSTRIDE + 2*c0);
            ulonglong2 q0 = wq[0];   // (w[c0] dup, w[c0+1] dup)
            ulonglong2 q1 = wq[1];   // c0+2, c0+3
            ulonglong2 q2 = wq[2];   // c0+4, c0+5
            ulonglong2 q3 = wq[3];   // c0+6, c0+7
            ull_t b2[4];
            #pragma unroll
            for (int j2 = 0; j2 < 4; j2++)
                b2[j2] = *(const ull_t*)(s_stage + k*256 + 2*px + 64*j2);   // LDS.64, conflict-free
            #pragma unroll
            for (int j2 = 0; j2 < 4; j2++) {
                FMAF2(acc2[0][j2], q0.x, b2[j2], acc2[0][j2]);
                FMAF2(acc2[1][j2], q0.y, b2[j2], acc2[1][j2]);
                FMAF2(acc2[2][j2], q1.x, b2[j2], acc2[2][j2]);
                FMAF2(acc2[3][j2], q1.y, b2[j2], acc2[3][j2]);
                FMAF2(acc2[4][j2], q2.x, b2[j2], acc2[4][j2]);
                FMAF2(acc2[5][j2], q2.y, b2[j2], acc2[5][j2]);
                FMAF2(acc2[6][j2], q3.x, b2[j2], acc2[6][j2]);
                FMAF2(acc2[7][j2], q3.y, b2[j2], acc2[7][j2]);
            }
        }
        __syncthreads();
    }

    float* ci = g_ci + (size_t)b * DIMC * HW;
    #pragma unroll
    for (int ii = 0; ii < 8; ii++)
        #pragma unroll
        for (int j2 = 0; j2 < 4; j2++)
            *(ull_t*)(ci + (c0 + ii)*256 + 2*px + 64*j2) = acc2[ii][j2];   // STG.64
}

// =====================================================================
// Kernel C: per-batch 3x3 conv, f32x2 packed.
// grid 1024 = 256 b x 4 o-groups(16 oc), 128 threads, 4 CTAs/SM.
// Output-position pairs (j,j+1); bv via 17-row register strip per (cl,kx);
// weights staged per-cc DUPLICATED [klocal][oc][2] -> LDS.128 = 2 operands.
// =====================================================================
#define C_SMEM_FLOATS (5184 + 4608 + 16 + 8)

__global__ void __launch_bounds__(128, 4)
conv_kernel(const int* __restrict__ question,
            const float* __restrict__ emb,
            const float* __restrict__ alpha,
            float* __restrict__ out_final,
            int mod)
{
    extern __shared__ float sm[];
    float* s_pad = sm;                 // 16 * 18*18 = 5184
    float* s_wcd = sm + 5184;          // 144 * 16 * 2 = 4608 (per-cc dup weights)
    float* s_cb  = sm + 5184 + 4608;   // 16
    float* s_a   = s_cb + 16;          // 3

    const int b   = blockIdx.x >> 2;
    const int og  = blockIdx.x & 3;
    const int tid = threadIdx.x;

    if (tid == 0) {
        float tmp[3], sf[3];
        for (int t = 0; t < 3; t++) tmp[t] = alpha[mod*3 + t];
        softmax_n(tmp, sf, 3);
        s_a[0] = sf[0]; s_a[1] = sf[1]; s_a[2] = sf[2];
    }
    __syncthreads();

    const float a0 = s_a[0], a1 = s_a[1], a2 = s_a[2];
    const float* r0 = emb + (size_t)question[b*3 + 0] * EMB_DIM;
    const float* r1 = emb + (size_t)question[b*3 + 1] * EMB_DIM;
    const float* r2 = emb + (size_t)question[b*3 + 2] * EMB_DIM;

    if (tid < 16) {
        const int o = og*16 + tid;
        s_cb[tid] = a0*r0[OFF_CNNB + o] + a1*r1[OFF_CNNB + o] + a2*r2[OFF_CNNB + o];
    }
    // zero padded stage once; halo stays zero across channel chunks
    for (int e = tid; e < 5184; e += 128) s_pad[e] = 0.f;
    __syncthreads();

    const int px = tid & 31;
    const int oy = tid >> 5;          // 0..3 -> 4 output channels each
    const int h0 = px >> 4;           // 0/1
    const int wi = px & 15;

    ull_t acc2[4][4];
    #pragma unroll
    for (int ii = 0; ii < 4; ii++)
        #pragma unroll
        for (int j2 = 0; j2 < 4; j2++) acc2[ii][j2] = 0ULL;   // (0.f, 0.f)

    const float4* ci4 = (const float4*)(g_ci + (size_t)b * DIMC * HW);
    const int wg = og*9216;

    for (int cc = 0; cc < 4; ++cc) {
        // stage 16 channels of ci into padded smem (centers only)
        for (int e4 = tid; e4 < 1024; e4 += 128) {
            float4 v = ci4[cc*1024 + e4];
            const int e  = e4 * 4;
            const int cl = e >> 8;
            const int h  = (e >> 4) & 15;
            const int w  = e & 15;
            float* dst = s_pad + cl*324 + (h + 1)*18 + (w + 1);
            dst[0] = v.x; dst[1] = v.y; dst[2] = v.z; dst[3] = v.w;
        }
        // stage this cc's weight slice, duplicated: s_wcd[klocal*32 + oc*2 {+0,+1}]
        for (int idx4 = tid; idx4 < 576; idx4 += 128) {
            const int oc = idx4 & 15;
            const int k4 = idx4 >> 4;      // 0..35
            const int goff = wg + oc*576 + cc*144 + k4*4;
            float4 x = *(const float4*)(r0 + goff);
            float4 y = *(const float4*)(r1 + goff);
            float4 z = *(const float4*)(r2 + goff);
            const int w = (k4*4)*32 + oc*2;
            float v;
            v = a0*x.x + a1*y.x + a2*z.x; s_wcd[w]      = v; s_wcd[w + 1]  = v;
            v = a0*x.y + a1*y.y + a2*z.y; s_wcd[w + 32] = v; s_wcd[w + 33] = v;
            v = a0*x.z + a1*y.z + a2*z.z; s_wcd[w + 64] = v; s_wcd[w + 65] = v;
            v = a0*x.w + a1*y.w + a2*z.w; s_wcd[w + 96] = v; s_wcd[w + 97] = v;
        }
        __syncthreads();

        const int base = h0*18 + wi;
        #pragma unroll 1
        for (int cl = 0; cl < 16; ++cl) {
            const float* pch = s_pad + cl*324 + base;
            #pragma unroll
            for (int kx = 0; kx < 3; ++kx) {
                // register strip: rows h0..h0+16 at column wi+kx
                float s[17];
                #pragma unroll
                for (int r = 0; r < 17; r++) s[r] = pch[r*18 + kx];
                #pragma unroll
                for (int ky = 0; ky < 3; ++ky) {
                    const int klocal = cl*9 + ky*3 + kx;
                    const ulonglong2* wq = (const ulonglong2*)(s_wcd + klocal*32 + oy*8);
                    ulonglong2 wA = wq[0];   // (w[oc0] dup, w[oc1] dup)
                    ulonglong2 wB = wq[1];   // (w[oc2] dup, w[oc3] dup)
                    #pragma unroll
                    for (int j2 = 0; j2 < 4; j2++) {
                        ull_t bv2;
                        PACKF2(bv2, s[4*j2 + ky], s[4*j2 + ky + 2]);
                        FMAF2(acc2[0][j2], wA.x, bv2, acc2[0][j2]);
                        FMAF2(acc2[1][j2], wA.y, bv2, acc2[1][j2]);
                        FMAF2(acc2[2][j2], wB.x, bv2, acc2[2][j2]);
                        FMAF2(acc2[3][j2], wB.y, bv2, acc2[3][j2]);
                    }
                }
            }
        }
        __syncthreads();
    }

    float* dst = (mod == 0) ? g_h1 : (mod == 1) ? g_h2 : out_final;
    dst += (size_t)b * DIMC * HW;
    #pragma unroll
    for (int ii = 0; ii < 4; ii++) {
        const int o = og*16 + oy*4 + ii;
        const float bb = s_cb[oy*4 + ii];
        #pragma unroll
        for (int j2 = 0; j2 < 4; j2++) {
            float lo, hi;
            UNPACKF2(lo, hi, acc2[ii][j2]);
            const int p = px + 64*j2;
            dst[o*256 + p]      = fmaxf(lo + bb, 0.f);
            dst[o*256 + p + 32] = fmaxf(hi + bb, 0.f);
        }
    }
}

// =====================================================================
extern "C" void kernel_launch(void* const* d_in, const int* in_sizes, int n_in,
                              void* d_out, int out_size)
{
    const int*   question = (const int*)  d_in[0];
    const float* img      = (const float*)d_in[1];
    const float* emb      = (const float*)d_in[2];
    const float* alpha    = (const float*)d_in[3];
    const float* tau0     = (const float*)d_in[4];
    const float* tau1     = (const float*)d_in[5];
    float* out = (float*)d_out;

    const int p_smem = P_SMEM_FLOATS * 4;
    const int c_smem = C_SMEM_FLOATS * 4;
    cudaFuncSetAttribute(proj_kernel, cudaFuncAttributeMaxDynamicSharedMemorySize, p_smem);
    cudaFuncSetAttribute(conv_kernel, cudaFuncAttributeMaxDynamicSharedMemorySize, c_smem);

    for (int mod = 0; mod < 3; ++mod) {
        proj_kernel<<<BATCH, 256, p_smem>>>(question, img, emb, alpha, tau0, tau1, mod);
        conv_kernel<<<BATCH*4, 128, c_smem>>>(question, emb, alpha, out, mod);
    }
    (void)in_sizes; (void)n_in; (void)out_size;
}

// round 4
// speedup vs baseline: 1.2523x; 1.2523x over previous
#include <cuda_runtime.h>
#include <math.h>

// ---------------- problem constants ----------------
#define DIMC      64
#define HW        256          // 16x16
#define BATCH     256
#define EMB_DIM   45184
#define OFF_CNNW  0
#define OFF_CNNB  36864
#define OFF_PROJW 36928
#define OFF_PROJB 45120
#define BHW       (BATCH*DIMC*HW)   // 4194304 floats = 16 MB

typedef unsigned long long ull_t;

// packed f32x2 helpers (sm_103a FFMA2 path — only reachable via PTX)
#define PACKF2(out, lo, hi) \
    asm("mov.b64 %0, {%1, %2};" : "=l"(out) : "f"(lo), "f"(hi))
#define UNPACKF2(lo, hi, in) \
    asm("mov.b64 {%0, %1}, %2;" : "=f"(lo), "=f"(hi) : "l"(in))
#define FMAF2(d, a, b, c) \
    asm("fma.rn.f32x2 %0, %1, %2, %3;" : "=l"(d) : "l"(a), "l"(b), "l"(c))

// scratch: module outputs h1,h2 and projected conv-input
__device__ float g_h1[BHW];
__device__ float g_h2[BHW];
__device__ float g_ci[BHW];

__device__ __forceinline__ void softmax_n(const float* x, float* y, int n) {
    float m = x[0];
    for (int i = 1; i < n; i++) m = fmaxf(m, x[i]);
    float s = 0.f;
    for (int i = 0; i < n; i++) { y[i] = expf(x[i] - m); s += y[i]; }
    float inv = 1.f / s;
    for (int i = 0; i < n; i++) y[i] *= inv;
}

// =====================================================================
// Kernel P: per-batch projection, f32x2, crossbar-balanced.
//   ci[b, c, p] = sum_j proj_w[b,c,j] * inp[b,j,p] + proj_b[b,c]
// grid 256 (1 CTA/batch), 256 threads, 2 CTAs/SM.
// Positions in x-pairs (2px, 2px+1): bv2 = direct conflict-free LDS.64.
// Weights k-major NON-dup (warp-uniform LDS.32 + register pack on alu pipe).
// =====================================================================
#define P_SMEM_FLOATS (16384 + 64*68 + 64 + 16)

__global__ void __launch_bounds__(256, 2)
proj_kernel(const int* __restrict__ question,
            const float* __restrict__ img,
            const float* __restrict__ emb,
            const float* __restrict__ alpha,
            const float* __restrict__ tau0,
            const float* __restrict__ tau1,
            int mod)
{
    extern __shared__ float sm[];
    float* s_stage = sm;                   // 64*256 = 16384
    float* s_wT    = sm + 16384;           // 64*68  = 4352 (k-major, padded)
    float* s_pb    = sm + 16384 + 4352;    // 64
    float* s_scal  = s_pb + 64;            // 9 scalars

    const int b   = blockIdx.x;
    const int tid = threadIdx.x;

    if (tid == 0) {
        float tmp[4], sf[4];
        for (int t = 0; t < 3; t++) tmp[t] = alpha[mod*3 + t];
        softmax_n(tmp, sf, 3);
        s_scal[0] = sf[0]; s_scal[1] = sf[1]; s_scal[2] = sf[2];
        const int n = mod + 2;
        for (int m = 0; m < n; m++) tmp[m] = tau0[mod*4 + m];
        softmax_n(tmp, sf, n);
        s_scal[3] = sf[1];
        s_scal[4] = (n > 2) ? sf[2] : 0.f;
        s_scal[5] = (n > 3) ? sf[3] : 0.f;
        for (int m = 0; m < n; m++) tmp[m] = tau1[mod*4 + m];
        softmax_n(tmp, sf, n);
        s_scal[6] = sf[1];
        s_scal[7] = (n > 2) ? sf[2] : 0.f;
        s_scal[8] = (n > 3) ? sf[3] : 0.f;
    }
    __syncthreads();

    const float a0 = s_scal[0], a1 = s_scal[1], a2 = s_scal[2];
    const float* r0 = emb + (size_t)question[b*3 + 0] * EMB_DIM;
    const float* r1 = emb + (size_t)question[b*3 + 1] * EMB_DIM;
    const float* r2 = emb + (size_t)question[b*3 + 2] * EMB_DIM;

    if (tid < 64)
        s_pb[tid] = a0*r0[OFF_PROJB + tid] + a1*r1[OFF_PROJB + tid] + a2*r2[OFF_PROJB + tid];

    const int px = tid & 31;
    const int c0 = (tid >> 5) * 8;
    ull_t acc2[8][4];

    const float4* img4 = (const float4*)(img  + (size_t)b * DIMC * HW);
    const float4* h14  = (const float4*)(g_h1 + (size_t)b * DIMC * HW);
    const float4* h24  = (const float4*)(g_h2 + (size_t)b * DIMC * HW);
    float4* stage4 = (float4*)s_stage;

    for (int half = 0; half < 2; ++half) {
        const float w1 = s_scal[3 + 3*half + 0];
        const float w2 = s_scal[3 + 3*half + 1];
        const float w3 = s_scal[3 + 3*half + 2];

        // stage = w1*img + w2*h1 + w3*h2   (64 ch x 256 pos)
        for (int e4 = tid; e4 < 4096; e4 += 256) {
            float4 v = img4[e4];
            float4 o;
            o.x = w1*v.x; o.y = w1*v.y; o.z = w1*v.z; o.w = w1*v.w;
            if (mod >= 1) { float4 u = h14[e4]; o.x += w2*u.x; o.y += w2*u.y; o.z += w2*u.z; o.w += w2*u.w; }
            if (mod >= 2) { float4 u = h24[e4]; o.x += w3*u.x; o.y += w3*u.y; o.z += w3*u.z; o.w += w3*u.w; }
            stage4[e4] = o;
        }
        // proj weight (this K-half), k-major: s_wT[k*68 + c]
        for (int e = tid; e < 4096; e += 256) {
            const int c  = e >> 6;
            const int kk = e & 63;
            const int off = OFF_PROJW + c*128 + half*64 + kk;
            s_wT[kk*68 + c] = a0*r0[off] + a1*r1[off] + a2*r2[off];
        }
        __syncthreads();

        if (half == 0) {
            #pragma unroll
            for (int ii = 0; ii < 8; ii++) {
                ull_t pbp;
                PACKF2(pbp, s_pb[c0 + ii], s_pb[c0 + ii]);
                #pragma unroll
                for (int j2 = 0; j2 < 4; j2++) acc2[ii][j2] = pbp;
            }
        }

        #pragma unroll 2
        for (int k = 0; k < 64; k++) {
            // weights: warp-uniform LDS.32 + register pack (alu pipe)
            ull_t a2r[8];
            #pragma unroll
            for (int ii = 0; ii < 8; ii++) {
                const float wv = s_wT[k*68 + c0 + ii];
                PACKF2(a2r[ii], wv, wv);
            }
            ull_t b2[4];
            #pragma unroll
            for (int j2 = 0; j2 < 4; j2++)
                b2[j2] = *(const ull_t*)(s_stage + k*256 + 2*px + 64*j2);  // LDS.64, conflict-free
            #pragma unroll
            for (int j2 = 0; j2 < 4; j2++)
                #pragma unroll
                for (int ii = 0; ii < 8; ii++)
                    FMAF2(acc2[ii][j2], a2r[ii], b2[j2], acc2[ii][j2]);
        }
        __syncthreads();
    }

    float* ci = g_ci + (size_t)b * DIMC * HW;
    #pragma unroll
    for (int ii = 0; ii < 8; ii++)
        #pragma unroll
        for (int j2 = 0; j2 < 4; j2++)
            *(ull_t*)(ci + (c0 + ii)*256 + 2*px + 64*j2) = acc2[ii][j2];   // STG.64
}

// =====================================================================
// Kernel C: per-batch 3x3 conv, f32x2, 8 oc/thread (crossbar-starved).
// grid 512 = 256 b x 2 og(32 oc), 128 threads, 3 CTAs/SM.
// Thread owns h = 8*h0 + j (contiguous block) -> 10-row strips, pairs (j,j+1).
// Weights NON-dup [klocal][oc] (stride 33): warp-uniform LDS.32 + reg pack.
// =====================================================================
#define CW_STRIDE 33
#define C_SMEM_FLOATS (5184 + 144*CW_STRIDE + 32 + 8)

__global__ void __launch_bounds__(128, 3)
conv_kernel(const int* __restrict__ question,
            const float* __restrict__ emb,
            const float* __restrict__ alpha,
            float* __restrict__ out_final,
            int mod)
{
    extern __shared__ float sm[];
    float* s_pad = sm;                        // 16 * 324 = 5184
    float* s_wc  = sm + 5184;                 // 144 * 33 = 4752
    float* s_cb  = sm + 5184 + 144*CW_STRIDE; // 32
    float* s_a   = s_cb + 32;                 // 3

    const int b   = blockIdx.x >> 1;
    const int og  = blockIdx.x & 1;
    const int tid = threadIdx.x;

    if (tid == 0) {
        float tmp[3], sf[3];
        for (int t = 0; t < 3; t++) tmp[t] = alpha[mod*3 + t];
        softmax_n(tmp, sf, 3);
        s_a[0] = sf[0]; s_a[1] = sf[1]; s_a[2] = sf[2];
    }
    __syncthreads();

    const float a0 = s_a[0], a1 = s_a[1], a2 = s_a[2];
    const float* r0 = emb + (size_t)question[b*3 + 0] * EMB_DIM;
    const float* r1 = emb + (size_t)question[b*3 + 1] * EMB_DIM;
    const float* r2 = emb + (size_t)question[b*3 + 2] * EMB_DIM;

    if (tid < 32) {
        const int o = og*32 + tid;
        s_cb[tid] = a0*r0[OFF_CNNB + o] + a1*r1[OFF_CNNB + o] + a2*r2[OFF_CNNB + o];
    }
    // zero padded stage once; halo stays zero across channel chunks
    for (int e = tid; e < 5184; e += 128) s_pad[e] = 0.f;
    __syncthreads();

    const int px = tid & 31;
    const int wq = tid >> 5;          // warp: oc block of 8
    const int ocb = wq * 8;           // og-local oc base
    const int h0 = px >> 4;           // 0/1 -> h block 8*h0..8*h0+7
    const int wi = px & 15;

    ull_t acc2[8][4];
    #pragma unroll
    for (int ii = 0; ii < 8; ii++)
        #pragma unroll
        for (int j2 = 0; j2 < 4; j2++) acc2[ii][j2] = 0ULL;

    const float4* ci4 = (const float4*)(g_ci + (size_t)b * DIMC * HW);
    const int wgoff = og * 32 * 576;  // weight offset for this og (OFF_CNNW = 0)

    for (int cc = 0; cc < 4; ++cc) {
        // stage 16 channels of ci into padded smem (centers only)
        for (int e4 = tid; e4 < 1024; e4 += 128) {
            float4 v = ci4[cc*1024 + e4];
            const int e  = e4 * 4;
            const int cl = e >> 8;
            const int h  = (e >> 4) & 15;
            const int w  = e & 15;
            float* dst = s_pad + cl*324 + (h + 1)*18 + (w + 1);
            dst[0] = v.x; dst[1] = v.y; dst[2] = v.z; dst[3] = v.w;
        }
        // stage this cc's weight slice NON-dup: s_wc[klocal*33 + oc_local]
        for (int idx = tid; idx < 32*36; idx += 128) {
            const int oc_l = idx / 36;
            const int k4   = idx % 36;
            const int goff = wgoff + oc_l*576 + cc*144 + k4*4;
            float4 x = *(const float4*)(r0 + goff);
            float4 y = *(const float4*)(r1 + goff);
            float4 z = *(const float4*)(r2 + goff);
            float* w = s_wc + (k4*4)*CW_STRIDE + oc_l;
            w[0]           = a0*x.x + a1*y.x + a2*z.x;
            w[CW_STRIDE]   = a0*x.y + a1*y.y + a2*z.y;
            w[2*CW_STRIDE] = a0*x.z + a1*y.z + a2*z.z;
            w[3*CW_STRIDE] = a0*x.w + a1*y.w + a2*z.w;
        }
        __syncthreads();

        #pragma unroll 1
        for (int cl = 0; cl < 16; ++cl) {
            const float* pbase = s_pad + cl*324 + h0*144 + wi;   // row 8*h0, col wi
            #pragma unroll
            for (int kx = 0; kx < 3; ++kx) {
                // 10-row strip at column wi+kx (conflict-free LDS.32)
                float s[10];
                #pragma unroll
                for (int r = 0; r < 10; r++) s[r] = pbase[r*18 + kx];
                #pragma unroll
                for (int ky = 0; ky < 3; ++ky) {
                    const int klocal = cl*9 + ky*3 + kx;
                    const float* wrow = s_wc + klocal*CW_STRIDE + ocb;
                    ull_t w2[8];
                    #pragma unroll
                    for (int ii = 0; ii < 8; ii++) {
                        const float wv = wrow[ii];     // warp-uniform broadcast
                        PACKF2(w2[ii], wv, wv);
                    }
                    #pragma unroll
                    for (int j2 = 0; j2 < 4; j2++) {
                        ull_t bv2;
                        PACKF2(bv2, s[2*j2 + ky], s[2*j2 + ky + 1]);
                        #pragma unroll
                        for (int ii = 0; ii < 8; ii++)
                            FMAF2(acc2[ii][j2], w2[ii], bv2, acc2[ii][j2]);
                    }
                }
            }
        }
        __syncthreads();
    }

    float* dst = (mod == 0) ? g_h1 : (mod == 1) ? g_h2 : out_final;
    dst += (size_t)b * DIMC * HW;
    #pragma unroll
    for (int ii = 0; ii < 8; ii++) {
        const int o = og*32 + ocb + ii;
        const float bb = s_cb[ocb + ii];
        #pragma unroll
        for (int j2 = 0; j2 < 4; j2++) {
            float lo, hi;
            UNPACKF2(lo, hi, acc2[ii][j2]);
            const int h = 8*h0 + 2*j2;
            dst[o*256 + h*16 + wi]        = fmaxf(lo + bb, 0.f);
            dst[o*256 + (h + 1)*16 + wi]  = fmaxf(hi + bb, 0.f);
        }
    }
}

// =====================================================================
extern "C" void kernel_launch(void* const* d_in, const int* in_sizes, int n_in,
                              void* d_out, int out_size)
{
    const int*   question = (const int*)  d_in[0];
    const float* img      = (const float*)d_in[1];
    const float* emb      = (const float*)d_in[2];
    const float* alpha    = (const float*)d_in[3];
    const float* tau0     = (const float*)d_in[4];
    const float* tau1     = (const float*)d_in[5];
    float* out = (float*)d_out;

    const int p_smem = P_SMEM_FLOATS * 4;
    const int c_smem = C_SMEM_FLOATS * 4;
    cudaFuncSetAttribute(proj_kernel, cudaFuncAttributeMaxDynamicSharedMemorySize, p_smem);
    cudaFuncSetAttribute(conv_kernel, cudaFuncAttributeMaxDynamicSharedMemorySize, c_smem);

    for (int mod = 0; mod < 3; ++mod) {
        proj_kernel<<<BATCH, 256, p_smem>>>(question, img, emb, alpha, tau0, tau1, mod);
        conv_kernel<<<BATCH*2, 128, c_smem>>>(question, emb, alpha, out, mod);
    }
    (void)in_sizes; (void)n_in; (void)out_size;
}

// round 6
// speedup vs baseline: 1.4813x; 1.1829x over previous
#include <cuda_runtime.h>
#include <math.h>

// ---------------- problem constants ----------------
#define DIMC      64
#define HW        256          // 16x16
#define BATCH     256
#define EMB_DIM   45184
#define OFF_CNNW  0
#define OFF_CNNB  36864
#define OFF_PROJW 36928
#define OFF_PROJB 45120
#define BHW       (BATCH*DIMC*HW)   // 4194304 floats = 16 MB

typedef unsigned long long ull_t;

// packed f32x2 helpers (sm_103a FFMA2 path — only reachable via PTX)
#define PACKF2(out, lo, hi) \
    asm("mov.b64 %0, {%1, %2};" : "=l"(out) : "f"(lo), "f"(hi))
#define UNPACKF2(lo, hi, in) \
    asm("mov.b64 {%0, %1}, %2;" : "=f"(lo), "=f"(hi) : "l"(in))
#define FMAF2(d, a, b, c) \
    asm("fma.rn.f32x2 %0, %1, %2, %3;" : "=l"(d) : "l"(a), "l"(b), "l"(c))

// scratch: module outputs h1,h2 and projected conv-input
__device__ float g_h1[BHW];
__device__ float g_h2[BHW];
__device__ float g_ci[BHW];

__device__ __forceinline__ void softmax_n(const float* x, float* y, int n) {
    float m = x[0];
    for (int i = 1; i < n; i++) m = fmaxf(m, x[i]);
    float s = 0.f;
    for (int i = 0; i < n; i++) { y[i] = expf(x[i] - m); s += y[i]; }
    float inv = 1.f / s;
    for (int i = 0; i < n; i++) y[i] *= inv;
}

// =====================================================================
// Kernel P: per-batch projection, f32x2 (unchanged from R4 — near floor).
// grid 256 (1 CTA/batch), 256 threads, 2 CTAs/SM, single wave.
// =====================================================================
#define P_SMEM_FLOATS (16384 + 64*68 + 64 + 16)

__global__ void __launch_bounds__(256, 2)
proj_kernel(const int* __restrict__ question,
            const float* __restrict__ img,
            const float* __restrict__ emb,
            const float* __restrict__ alpha,
            const float* __restrict__ tau0,
            const float* __restrict__ tau1,
            int mod)
{
    extern __shared__ float sm[];
    float* s_stage = sm;                   // 64*256 = 16384
    float* s_wT    = sm + 16384;           // 64*68  = 4352 (k-major, padded)
    float* s_pb    = sm + 16384 + 4352;    // 64
    float* s_scal  = s_pb + 64;            // 9 scalars

    const int b   = blockIdx.x;
    const int tid = threadIdx.x;

    if (tid == 0) {
        float tmp[4], sf[4];
        for (int t = 0; t < 3; t++) tmp[t] = alpha[mod*3 + t];
        softmax_n(tmp, sf, 3);
        s_scal[0] = sf[0]; s_scal[1] = sf[1]; s_scal[2] = sf[2];
        const int n = mod + 2;
        for (int m = 0; m < n; m++) tmp[m] = tau0[mod*4 + m];
        softmax_n(tmp, sf, n);
        s_scal[3] = sf[1];
        s_scal[4] = (n > 2) ? sf[2] : 0.f;
        s_scal[5] = (n > 3) ? sf[3] : 0.f;
        for (int m = 0; m < n; m++) tmp[m] = tau1[mod*4 + m];
        softmax_n(tmp, sf, n);
        s_scal[6] = sf[1];
        s_scal[7] = (n > 2) ? sf[2] : 0.f;
        s_scal[8] = (n > 3) ? sf[3] : 0.f;
    }
    __syncthreads();

    const float a0 = s_scal[0], a1 = s_scal[1], a2 = s_scal[2];
    const float* r0 = emb + (size_t)question[b*3 + 0] * EMB_DIM;
    const float* r1 = emb + (size_t)question[b*3 + 1] * EMB_DIM;
    const float* r2 = emb + (size_t)question[b*3 + 2] * EMB_DIM;

    if (tid < 64)
        s_pb[tid] = a0*r0[OFF_PROJB + tid] + a1*r1[OFF_PROJB + tid] + a2*r2[OFF_PROJB + tid];

    const int px = tid & 31;
    const int c0 = (tid >> 5) * 8;
    ull_t acc2[8][4];

    const float4* img4 = (const float4*)(img  + (size_t)b * DIMC * HW);
    const float4* h14  = (const float4*)(g_h1 + (size_t)b * DIMC * HW);
    const float4* h24  = (const float4*)(g_h2 + (size_t)b * DIMC * HW);
    float4* stage4 = (float4*)s_stage;

    for (int half = 0; half < 2; ++half) {
        const float w1 = s_scal[3 + 3*half + 0];
        const float w2 = s_scal[3 + 3*half + 1];
        const float w3 = s_scal[3 + 3*half + 2];

        for (int e4 = tid; e4 < 4096; e4 += 256) {
            float4 v = img4[e4];
            float4 o;
            o.x = w1*v.x; o.y = w1*v.y; o.z = w1*v.z; o.w = w1*v.w;
            if (mod >= 1) { float4 u = h14[e4]; o.x += w2*u.x; o.y += w2*u.y; o.z += w2*u.z; o.w += w2*u.w; }
            if (mod >= 2) { float4 u = h24[e4]; o.x += w3*u.x; o.y += w3*u.y; o.z += w3*u.z; o.w += w3*u.w; }
            stage4[e4] = o;
        }
        for (int e = tid; e < 4096; e += 256) {
            const int c  = e >> 6;
            const int kk = e & 63;
            const int off = OFF_PROJW + c*128 + half*64 + kk;
            s_wT[kk*68 + c] = a0*r0[off] + a1*r1[off] + a2*r2[off];
        }
        __syncthreads();

        if (half == 0) {
            #pragma unroll
            for (int ii = 0; ii < 8; ii++) {
                ull_t pbp;
                PACKF2(pbp, s_pb[c0 + ii], s_pb[c0 + ii]);
                #pragma unroll
                for (int j2 = 0; j2 < 4; j2++) acc2[ii][j2] = pbp;
            }
        }

        #pragma unroll 2
        for (int k = 0; k < 64; k++) {
            ull_t a2r[8];
            #pragma unroll
            for (int ii = 0; ii < 8; ii++) {
                const float wv = s_wT[k*68 + c0 + ii];
                PACKF2(a2r[ii], wv, wv);
            }
            ull_t b2[4];
            #pragma unroll
            for (int j2 = 0; j2 < 4; j2++)
                b2[j2] = *(const ull_t*)(s_stage + k*256 + 2*px + 64*j2);  // LDS.64, conflict-free
            #pragma unroll
            for (int j2 = 0; j2 < 4; j2++)
                #pragma unroll
                for (int ii = 0; ii < 8; ii++)
                    FMAF2(acc2[ii][j2], a2r[ii], b2[j2], acc2[ii][j2]);
        }
        __syncthreads();
    }

    float* ci = g_ci + (size_t)b * DIMC * HW;
    #pragma unroll
    for (int ii = 0; ii < 8; ii++)
        #pragma unroll
        for (int j2 = 0; j2 < 4; j2++)
            *(ull_t*)(ci + (c0 + ii)*256 + 2*px + 64*j2) = acc2[ii][j2];   // STG.64
}

// =====================================================================
// Kernel C: per-batch 3x3 conv, f32x2, oc-paired accumulators.
// grid 512 = 256 b x 2 og(32 oc), 128 threads, 4 CTAs/SM -> SINGLE WAVE.
// Pad stage TRANSPOSED [c][w][h]: strips = aligned conflict-free LDS.64.
// Weights [klocal][oc] stride 34: oc-pair via one warp-uniform LDS.64,
// zero weight packs; bv = dup-pack (alu pipe).
// =====================================================================
#define CW_STRIDE 34
#define C_SMEM_FLOATS (5184 + 144*CW_STRIDE + 32 + 8)

__global__ void __launch_bounds__(128, 4)
conv_kernel(const int* __restrict__ question,
            const float* __restrict__ emb,
            const float* __restrict__ alpha,
            float* __restrict__ out_final,
            int mod)
{
    extern __shared__ float sm[];
    float* s_pad = sm;                        // 16 * 324 (transposed [c][w18][h18])
    float* s_wc  = sm + 5184;                 // 144 * 34 = 4896
    float* s_cb  = sm + 5184 + 144*CW_STRIDE; // 32
    float* s_a   = s_cb + 32;                 // 3

    const int b   = blockIdx.x >> 1;
    const int og  = blockIdx.x & 1;
    const int tid = threadIdx.x;

    if (tid == 0) {
        float tmp[3], sf[3];
        for (int t = 0; t < 3; t++) tmp[t] = alpha[mod*3 + t];
        softmax_n(tmp, sf, 3);
        s_a[0] = sf[0]; s_a[1] = sf[1]; s_a[2] = sf[2];
    }
    __syncthreads();

    const float a0 = s_a[0], a1 = s_a[1], a2 = s_a[2];
    const float* r0 = emb + (size_t)question[b*3 + 0] * EMB_DIM;
    const float* r1 = emb + (size_t)question[b*3 + 1] * EMB_DIM;
    const float* r2 = emb + (size_t)question[b*3 + 2] * EMB_DIM;

    if (tid < 32) {
        const int o = og*32 + tid;
        s_cb[tid] = a0*r0[OFF_CNNB + o] + a1*r1[OFF_CNNB + o] + a2*r2[OFF_CNNB + o];
    }
    // zero padded stage once; halo stays zero across channel chunks
    for (int e = tid; e < 5184; e += 128) s_pad[e] = 0.f;
    __syncthreads();

    const int px  = tid & 31;
    const int wq  = tid >> 5;          // warp -> oc block of 8
    const int ocb = wq * 8;            // og-local oc base (even)
    const int h0  = px >> 4;           // 0/1 -> h block 8*h0..8*h0+7
    const int wi  = px & 15;

    ull_t acc2[4][8];                  // [oc-pair][h index r]
    #pragma unroll
    for (int i = 0; i < 4; i++)
        #pragma unroll
        for (int r = 0; r < 8; r++) acc2[i][r] = 0ULL;

    const float4* ci4 = (const float4*)(g_ci + (size_t)b * DIMC * HW);
    const int wgoff = og * 32 * 576;   // weight offset for this og (OFF_CNNW = 0)

    for (int cc = 0; cc < 4; ++cc) {
        // stage 16 channels of ci into TRANSPOSED padded smem [c][w+1][h+1]
        for (int e4 = tid; e4 < 1024; e4 += 128) {
            float4 v = ci4[cc*1024 + e4];
            const int e  = e4 * 4;
            const int cl = e >> 8;
            const int h  = (e >> 4) & 15;
            const int w  = e & 15;
            float* dstp = s_pad + cl*324 + (w + 1)*18 + (h + 1);
            dstp[0]  = v.x;            // w,   h
            dstp[18] = v.y;            // w+1, h
            dstp[36] = v.z;
            dstp[54] = v.w;
        }
        // stage this cc's weight slice: s_wc[klocal*34 + oc_local]
        for (int idx = tid; idx < 32*36; idx += 128) {
            const int oc_l = idx / 36;
            const int k4   = idx % 36;
            const int goff = wgoff + oc_l*576 + cc*144 + k4*4;
            float4 x = *(const float4*)(r0 + goff);
            float4 y = *(const float4*)(r1 + goff);
            float4 z = *(const float4*)(r2 + goff);
            float* w = s_wc + (k4*4)*CW_STRIDE + oc_l;
            w[0]           = a0*x.x + a1*y.x + a2*z.x;
            w[CW_STRIDE]   = a0*x.y + a1*y.y + a2*z.y;
            w[2*CW_STRIDE] = a0*x.z + a1*y.z + a2*z.z;
            w[3*CW_STRIDE] = a0*x.w + a1*y.w + a2*z.w;
        }
        __syncthreads();

        #pragma unroll 1
        for (int cl = 0; cl < 16; ++cl) {
            const float* chb = s_pad + cl*324 + 8*h0;
            #pragma unroll
            for (int kx = 0; kx < 3; ++kx) {
                // strip: rows 8h0..8h0+9 at column wi+kx, as 5 aligned float2
                const float2* sp = (const float2*)(chb + (wi + kx)*18);
                float2 s2[5];
                #pragma unroll
                for (int r = 0; r < 5; r++) s2[r] = sp[r];    // LDS.64, 2-phase CF
                const float sv[10] = { s2[0].x, s2[0].y, s2[1].x, s2[1].y, s2[2].x,
                                       s2[2].y, s2[3].x, s2[3].y, s2[4].x, s2[4].y };
                #pragma unroll
                for (int ky = 0; ky < 3; ++ky) {
                    const int klocal = cl*9 + ky*3 + kx;
                    const ull_t* wp = (const ull_t*)(s_wc + klocal*CW_STRIDE + ocb);
                    ull_t w2[4];
                    #pragma unroll
                    for (int i = 0; i < 4; i++) w2[i] = wp[i];  // uniform LDS.64, no pack
                    #pragma unroll
                    for (int r = 0; r < 8; r++) {
                        ull_t bv;
                        PACKF2(bv, sv[r + ky], sv[r + ky]);     // dup pack (alu)
                        #pragma unroll
                        for (int i = 0; i < 4; i++)
                            FMAF2(acc2[i][r], w2[i], bv, acc2[i][r]);
                    }
                }
            }
        }
        __syncthreads();
    }

    float* dst = (mod == 0) ? g_h1 : (mod == 1) ? g_h2 : out_final;
    dst += (size_t)b * DIMC * HW;
    #pragma unroll
    for (int i = 0; i < 4; i++) {
        const int o0 = og*32 + ocb + 2*i;
        const float b0v = s_cb[ocb + 2*i];
        const float b1v = s_cb[ocb + 2*i + 1];
        #pragma unroll
        for (int r = 0; r < 8; r++) {
            float lo, hi;
            UNPACKF2(lo, hi, acc2[i][r]);
            const int pos = (8*h0 + r)*16 + wi;
            dst[o0*256 + pos]       = fmaxf(lo + b0v, 0.f);
            dst[(o0 + 1)*256 + pos] = fmaxf(hi + b1v, 0.f);
        }
    }
}

// =====================================================================
extern "C" void kernel_launch(void* const* d_in, const int* in_sizes, int n_in,
                              void* d_out, int out_size)
{
    const int*   question = (const int*)  d_in[0];
    const float* img      = (const float*)d_in[1];
    const float* emb      = (const float*)d_in[2];
    const float* alpha    = (const float*)d_in[3];
    const float* tau0     = (const float*)d_in[4];
    const float* tau1     = (const float*)d_in[5];
    float* out = (float*)d_out;

    const int p_smem = P_SMEM_FLOATS * 4;
    const int c_smem = C_SMEM_FLOATS * 4;
    cudaFuncSetAttribute(proj_kernel, cudaFuncAttributeMaxDynamicSharedMemorySize, p_smem);
    cudaFuncSetAttribute(conv_kernel, cudaFuncAttributeMaxDynamicSharedMemorySize, c_smem);

    for (int mod = 0; mod < 3; ++mod) {
        proj_kernel<<<BATCH, 256, p_smem>>>(question, img, emb, alpha, tau0, tau1, mod);
        conv_kernel<<<BATCH*2, 128, c_smem>>>(question, emb, alpha, out, mod);
    }
    (void)in_sizes; (void)n_in; (void)out_size;
}